// round 14
// baseline (speedup 1.0000x reference)
#include <cuda_runtime.h>
#include <cuda_fp16.h>
#include <math.h>

#define Bn   16
#define Nn   1024
#define Dn   128
#define CAP  256     // max edges per row (mean ~52)

// ---------------- scratch (static device globals; no allocation) ----------------
__device__ __align__(16) float  d_h   [Bn*Nn*Dn];
__device__ __align__(16) __half d_hh  [Bn*Nn*Dn];    // half copy of h for gathers
__device__ __align__(16) float  d_g   [Bn*Nn*Dn];    // g' = h (A + A^T)
__device__ float  d_hdot[Bn*Nn];
__device__ int    d_colidx[Bn*Nn*CAP];
__device__ float  d_eval  [Bn*Nn*CAP];
__device__ int    d_rowcnt[Bn*Nn];
__device__ float  d_colZ  [Bn*Nn];
__device__ float  d_colinv[Bn*Nn];
__device__ __align__(16) __half d_r1h[Bn*Nn*Dn];
__device__ __align__(16) __half d_r2h[Bn*Nn*Dn];

// ---------------- packed fp32x2 FMA helpers (sm_100+) ----------------
__device__ __forceinline__ unsigned long long ffma2(unsigned long long a,
                                                    unsigned long long b,
                                                    unsigned long long c) {
    unsigned long long d;
    asm("fma.rn.f32x2 %0, %1, %2, %3;" : "=l"(d) : "l"(a), "l"(b), "l"(c));
    return d;
}
__device__ __forceinline__ unsigned long long pack2(float x) {
    unsigned long long d;
    asm("mov.b64 %0, {%1, %1};" : "=l"(d) : "f"(x));
    return d;
}
__device__ __forceinline__ unsigned long long packxy(float x, float y) {
    unsigned long long d;
    asm("mov.b64 %0, {%1, %2};" : "=l"(d) : "f"(x), "f"(y));
    return d;
}
__device__ __forceinline__ void unpack2(float& x, float& y, unsigned long long d) {
    asm("mov.b64 {%0, %1}, %2;" : "=f"(x), "=f"(y) : "l"(d));
}
union F4U { float4 f; unsigned long long u[2]; };

// ---------------- init: colZ starts at N ----------------
__global__ void k_init() {
    int t = blockIdx.x * blockDim.x + threadIdx.x;
    if (t < Bn*Nn) d_colZ[t] = (float)Nn;
}

// ================= dense GEMMs: 8 rows x 8 outs per thread, f32x2 math =================
#define KH_ROWS   64
#define KH_GRID   (Bn*Nn/KH_ROWS)      // 256
#define XT_STRIDE 68
#define KH_SMEM   ((128*132 + 128*XT_STRIDE + 128)*4)

// ---------------- k_h: h = x W^T + b (fp32 + half copy) ----------------
__global__ void __launch_bounds__(128) k_h(const float* __restrict__ x,
                                           const float* __restrict__ Ww,
                                           const float* __restrict__ Wb) {
    extern __shared__ float sm[];
    float* Wt = sm;                   // [128][132]  Wt[d][o] = W[o][d]
    float* xT = sm + 128*132;         // [128][68]

    const int t = threadIdx.x;
    const int ci = t & 15, ri = t >> 4;
    const int r0 = blockIdx.x * KH_ROWS;

    for (int i = t; i < 128*32; i += 128) {
        int o4 = i >> 7, d = i & 127;
        float4 v;
        v.x = Ww[(o4*4+0)*128 + d];
        v.y = Ww[(o4*4+1)*128 + d];
        v.z = Ww[(o4*4+2)*128 + d];
        v.w = Ww[(o4*4+3)*128 + d];
        *(float4*)&Wt[d*132 + o4*4] = v;
    }
    for (int i = t; i < 128*16; i += 128) {
        int row4 = i >> 7, k = i & 127;
        float4 v;
        v.x = x[(size_t)(r0+row4*4+0)*Dn + k];
        v.y = x[(size_t)(r0+row4*4+1)*Dn + k];
        v.z = x[(size_t)(r0+row4*4+2)*Dn + k];
        v.w = x[(size_t)(r0+row4*4+3)*Dn + k];
        *(float4*)&xT[k*XT_STRIDE + row4*4] = v;
    }
    __syncthreads();

    const float4 bA = *(const float4*)&Wb[ci*4];
    const float4 bB = *(const float4*)&Wb[64 + ci*4];
    unsigned long long acc[8][4];
    #pragma unroll
    for (int r = 0; r < 8; r++) {
        acc[r][0] = packxy(bA.x, bA.y);
        acc[r][1] = packxy(bA.z, bA.w);
        acc[r][2] = packxy(bB.x, bB.y);
        acc[r][3] = packxy(bB.z, bB.w);
    }

    #pragma unroll 4
    for (int k = 0; k < 128; k++) {
        F4U w0, w1;
        w0.f = *(float4*)&Wt[k*132 + ci*4];
        w1.f = *(float4*)&Wt[k*132 + 64 + ci*4];
        float4 xa = *(float4*)&xT[k*XT_STRIDE + ri*4];
        float4 xb = *(float4*)&xT[k*XT_STRIDE + 32 + ri*4];
        unsigned long long xp[8];
        xp[0] = pack2(xa.x); xp[1] = pack2(xa.y); xp[2] = pack2(xa.z); xp[3] = pack2(xa.w);
        xp[4] = pack2(xb.x); xp[5] = pack2(xb.y); xp[6] = pack2(xb.z); xp[7] = pack2(xb.w);
        #pragma unroll
        for (int r = 0; r < 8; r++) {
            acc[r][0] = ffma2(xp[r], w0.u[0], acc[r][0]);
            acc[r][1] = ffma2(xp[r], w0.u[1], acc[r][1]);
            acc[r][2] = ffma2(xp[r], w1.u[0], acc[r][2]);
            acc[r][3] = ffma2(xp[r], w1.u[1], acc[r][3]);
        }
    }

    #pragma unroll
    for (int r = 0; r < 8; r++) {
        const int row = r0 + ((r < 4) ? (ri*4 + r) : (32 + ri*4 + (r-4)));
        float o0,o1,o2,o3,p0,p1,p2,p3;
        unpack2(o0,o1,acc[r][0]); unpack2(o2,o3,acc[r][1]);
        unpack2(p0,p1,acc[r][2]); unpack2(p2,p3,acc[r][3]);
        *(float4*)&d_h[(size_t)row*Dn + ci*4]      = make_float4(o0,o1,o2,o3);
        *(float4*)&d_h[(size_t)row*Dn + 64 + ci*4] = make_float4(p0,p1,p2,p3);
        __half2 q0 = __floats2half2_rn(o0,o1), q1 = __floats2half2_rn(o2,o3);
        __half2 q2 = __floats2half2_rn(p0,p1), q3 = __floats2half2_rn(p2,p3);
        uint2 s0, s1;
        s0.x = *reinterpret_cast<unsigned*>(&q0); s0.y = *reinterpret_cast<unsigned*>(&q1);
        s1.x = *reinterpret_cast<unsigned*>(&q2); s1.y = *reinterpret_cast<unsigned*>(&q3);
        *(uint2*)&d_hh[(size_t)row*Dn + ci*4]      = s0;
        *(uint2*)&d_hh[(size_t)row*Dn + 64 + ci*4] = s1;
    }
}

// ---------------- k_g: g' = h (A + A^T) ; hdot = h.gw[0:128] + gb ----------------
__global__ void __launch_bounds__(128) k_g(const float* __restrict__ Am,
                                           const float* __restrict__ gw,
                                           const float* __restrict__ gb) {
    extern __shared__ float sm[];
    float* Ss = sm;                   // [128][132]
    float* hT = sm + 128*132;         // [128][68]
    float* gws = sm + 128*132 + 128*XT_STRIDE;

    const int t = threadIdx.x;
    const int ci = t & 15, ri = t >> 4;
    const int r0 = blockIdx.x * KH_ROWS;

    if (t < 128) gws[t] = gw[t];
    for (int i = t; i < 128*32; i += 128) {
        int o4 = i >> 7, d = i & 127;
        float4 a = *(const float4*)&Am[d*128 + o4*4];
        float4 v;
        v.x = a.x + Am[(o4*4+0)*128 + d];
        v.y = a.y + Am[(o4*4+1)*128 + d];
        v.z = a.z + Am[(o4*4+2)*128 + d];
        v.w = a.w + Am[(o4*4+3)*128 + d];
        *(float4*)&Ss[d*132 + o4*4] = v;
    }
    for (int i = t; i < 128*16; i += 128) {
        int row4 = i >> 7, k = i & 127;
        float4 v;
        v.x = d_h[(size_t)(r0+row4*4+0)*Dn + k];
        v.y = d_h[(size_t)(r0+row4*4+1)*Dn + k];
        v.z = d_h[(size_t)(r0+row4*4+2)*Dn + k];
        v.w = d_h[(size_t)(r0+row4*4+3)*Dn + k];
        *(float4*)&hT[k*XT_STRIDE + row4*4] = v;
    }
    __syncthreads();

    unsigned long long acc[8][4];
    #pragma unroll
    for (int r = 0; r < 8; r++)
        acc[r][0] = acc[r][1] = acc[r][2] = acc[r][3] = 0ull;

    #pragma unroll 4
    for (int k = 0; k < 128; k++) {
        F4U w0, w1;
        w0.f = *(float4*)&Ss[k*132 + ci*4];
        w1.f = *(float4*)&Ss[k*132 + 64 + ci*4];
        float4 xa = *(float4*)&hT[k*XT_STRIDE + ri*4];
        float4 xb = *(float4*)&hT[k*XT_STRIDE + 32 + ri*4];
        unsigned long long xp[8];
        xp[0] = pack2(xa.x); xp[1] = pack2(xa.y); xp[2] = pack2(xa.z); xp[3] = pack2(xa.w);
        xp[4] = pack2(xb.x); xp[5] = pack2(xb.y); xp[6] = pack2(xb.z); xp[7] = pack2(xb.w);
        #pragma unroll
        for (int r = 0; r < 8; r++) {
            acc[r][0] = ffma2(xp[r], w0.u[0], acc[r][0]);
            acc[r][1] = ffma2(xp[r], w0.u[1], acc[r][1]);
            acc[r][2] = ffma2(xp[r], w1.u[0], acc[r][2]);
            acc[r][3] = ffma2(xp[r], w1.u[1], acc[r][3]);
        }
    }

    #pragma unroll
    for (int r = 0; r < 8; r++) {
        const int row = r0 + ((r < 4) ? (ri*4 + r) : (32 + ri*4 + (r-4)));
        float o0,o1,o2,o3,p0,p1,p2,p3;
        unpack2(o0,o1,acc[r][0]); unpack2(o2,o3,acc[r][1]);
        unpack2(p0,p1,acc[r][2]); unpack2(p2,p3,acc[r][3]);
        *(float4*)&d_g[(size_t)row*Dn + ci*4]      = make_float4(o0,o1,o2,o3);
        *(float4*)&d_g[(size_t)row*Dn + 64 + ci*4] = make_float4(p0,p1,p2,p3);
    }

    if (t < KH_ROWS) {
        float p = 0.0f;
        #pragma unroll 8
        for (int k = 0; k < 128; k++)
            p += hT[k*XT_STRIDE + t] * gws[k];
        d_hdot[r0 + t] = p + gb[0];
    }
}

// ---------------- fused: atomic-free CSR + HFMA2 edge score (8 loads in flight) ----------------
__global__ void __launch_bounds__(128) k_buildE(const float* __restrict__ adj) {
    const int i = blockIdx.x, b = blockIdx.y;
    const int row = b*Nn + i;
    __shared__ int   cols[CAP];
    __shared__ float P[128];
    __shared__ int   wtot[4];
    const int t = threadIdx.x, lane = t & 31, warp = t >> 5;
    P[t] = d_g[(size_t)row*Dn + t];

    // ---- register-bitmask CSR build ----
    const float4* a4 = (const float4*)(adj + (size_t)row * Nn);
    const float4 v0 = a4[t];
    const float4 v1 = a4[t + 128];
    unsigned my = 0;
    my |= (v0.x > 0.0f) ? 1u   : 0u;
    my |= (v0.y > 0.0f) ? 2u   : 0u;
    my |= (v0.z > 0.0f) ? 4u   : 0u;
    my |= (v0.w > 0.0f) ? 8u   : 0u;
    my |= (v1.x > 0.0f) ? 16u  : 0u;
    my |= (v1.y > 0.0f) ? 32u  : 0u;
    my |= (v1.z > 0.0f) ? 64u  : 0u;
    my |= (v1.w > 0.0f) ? 128u : 0u;
    const int mycnt = __popc(my);

    int pre = mycnt;
    #pragma unroll
    for (int off = 1; off < 32; off <<= 1) {
        int nn = __shfl_up_sync(~0u, pre, off);
        if (lane >= off) pre += nn;
    }
    if (lane == 31) wtot[warp] = pre;
    __syncthreads();

    int base = pre - mycnt;
    int n = 0;
    #pragma unroll
    for (int w = 0; w < 4; w++) {
        int c = wtot[w];
        if (w < warp) base += c;
        n += c;
    }
    if (n > CAP) n = CAP;

    {
        int slot = base;
        #pragma unroll
        for (int j = 0; j < 8; j++) {
            if (my & (1u << j)) {
                int col = (j < 4) ? (t*4 + j) : ((t + 128)*4 + (j - 4));
                if (slot < CAP) cols[slot] = col;
                slot++;
            }
        }
    }
    __syncthreads();

    const int n8 = (n + 7) & ~7;
    if (t == 0) d_rowcnt[row] = n8;
    for (int s = t; s < n; s += 128) d_colidx[(size_t)row*CAP + s] = cols[s];
    for (int s = n + t; s < n8; s += 128) {
        d_colidx[(size_t)row*CAP + s] = 0;
        d_eval  [(size_t)row*CAP + s] = 0.0f;
    }

    // ---- scoring: half2 row slice, 4 edges / 8 uint4 loads in flight ----
    const int lo8 = lane & 7, grp = lane >> 3;
    __half2 rg2[8];
    #pragma unroll
    for (int k = 0; k < 2; k++)
        #pragma unroll
        for (int j = 0; j < 4; j++)
            rg2[k*4+j] = __floats2half2_rn(P[k*64 + lo8*8 + j*2],
                                           P[k*64 + lo8*8 + j*2 + 1]);

    const __half* hb = d_hh + (size_t)b*Nn*Dn;
    const __half2 z2 = __floats2half2_rn(0.0f, 0.0f);
    for (int s0 = warp*4; s0 < n; s0 += 64) {
        int sx[4], cx[4];
        #pragma unroll
        for (int e = 0; e < 4; e++) {
            sx[e] = s0 + grp + e*16;
            cx[e] = cols[(sx[e] < n) ? sx[e] : 0];
        }
        uint4 ra[4], rbq[4];
        #pragma unroll
        for (int e = 0; e < 4; e++) {
            ra[e]  = *(const uint4*)&hb[(size_t)cx[e]*Dn +      lo8*8];
            rbq[e] = *(const uint4*)&hb[(size_t)cx[e]*Dn + 64 + lo8*8];
        }
        #pragma unroll
        for (int e = 0; e < 4; e++) {
            const __half2* h0 = (const __half2*)&ra[e];
            const __half2* h1 = (const __half2*)&rbq[e];
            __half2 acc = z2;
            #pragma unroll
            for (int j = 0; j < 4; j++) {
                acc = __hfma2(rg2[j],   h0[j], acc);
                acc = __hfma2(rg2[4+j], h1[j], acc);
            }
            float2 f = __half22float2(acc);
            float p = f.x + f.y;
            p += __shfl_xor_sync(~0u, p, 1);
            p += __shfl_xor_sync(~0u, p, 2);
            p += __shfl_xor_sync(~0u, p, 4);
            if (lo8 == 0 && sx[e] < n) {
                float ev = __expf(p);
                d_eval[(size_t)row*CAP + sx[e]] = ev;
                atomicAdd(&d_colZ[b*Nn + cx[e]], ev - 1.0f);
            }
        }
    }
}

// ---------------- finalize: colinv = 1 / Z ----------------
__global__ void k_colfinal() {
    int t = blockIdx.x * blockDim.x + threadIdx.x;
    if (t < Bn*Nn)
        d_colinv[t] = 1.0f / d_colZ[t];
}

// ---------------- normalize all edge attention values in place ----------------
__global__ void k_attnorm() {
    const int lane = threadIdx.x & 31, warp = threadIdx.x >> 5;
    const int row  = blockIdx.x * 8 + warp;
    const int b    = row >> 10;
    const int n8   = d_rowcnt[row];
    const int*  ci = d_colidx + (size_t)row * CAP;
    float*      ev = d_eval   + (size_t)row * CAP;
    const float* cinv = d_colinv + b*Nn;
    for (int s = lane; s < n8; s += 32)
        ev[s] *= cinv[ci[s]];
}

// ---------------- hop: warp/row, smem-staged indices, 8 gathers in flight ----------------
__global__ void __launch_bounds__(256) k_hop(int which, const float* __restrict__ gw,
                                             float* __restrict__ outbuf) {
    const __half* rin = (which == 0) ? d_hh : (which == 1 ? d_r1h : d_r2h);
    __half* routh = (which == 0) ? d_r1h : d_r2h;

    __shared__ int   s_ci[8][CAP];
    __shared__ float s_ev[8][CAP];

    const int lane = threadIdx.x & 31, warp = threadIdx.x >> 5;
    const int row  = blockIdx.x * 8 + warp;
    const int b    = row >> 10;
    const int hw   = lane >> 4;
    const int lo   = lane & 15;

    const __half* rb = rin + (size_t)b * Nn * Dn;
    const int    n8  = d_rowcnt[row];
    {
        const int*   ci = d_colidx + (size_t)row * CAP;
        const float* ev = d_eval   + (size_t)row * CAP;
        for (int s = lane; s < n8; s += 32) {
            s_ci[warp][s] = ci[s];
            s_ev[warp][s] = ev[s];
        }
        __syncwarp();
    }

    float acc[8];
    #pragma unroll
    for (int j = 0; j < 8; j++) acc[j] = 0.0f;

    int s = 0;
    // main loop: 16 edges per step, 8 gathers in flight per thread
    for (; s + 16 <= n8; s += 16) {
        int cx[8]; float vx[8];
        #pragma unroll
        for (int u = 0; u < 8; u++) {
            const int sxx = s + u*2 + hw;
            cx[u] = s_ci[warp][sxx];
            vx[u] = s_ev[warp][sxx];
        }
        uint4 raw[8];
        #pragma unroll
        for (int u = 0; u < 8; u++)
            raw[u] = *(const uint4*)&rb[(size_t)cx[u]*Dn + lo*8];
        #pragma unroll
        for (int u = 0; u < 8; u++) {
            const __half2* h2 = (const __half2*)&raw[u];
            #pragma unroll
            for (int j = 0; j < 4; j++) {
                float2 f = __half22float2(h2[j]);
                acc[j*2]   += vx[u] * f.x;
                acc[j*2+1] += vx[u] * f.y;
            }
        }
    }
    // tail: 8 edges
    for (; s < n8; s += 8) {
        int cx[4]; float vx[4];
        #pragma unroll
        for (int u = 0; u < 4; u++) {
            const int sxx = s + u*2 + hw;
            cx[u] = s_ci[warp][sxx];
            vx[u] = s_ev[warp][sxx];
        }
        uint4 raw[4];
        #pragma unroll
        for (int u = 0; u < 4; u++)
            raw[u] = *(const uint4*)&rb[(size_t)cx[u]*Dn + lo*8];
        #pragma unroll
        for (int u = 0; u < 4; u++) {
            const __half2* h2 = (const __half2*)&raw[u];
            #pragma unroll
            for (int j = 0; j < 4; j++) {
                float2 f = __half22float2(h2[j]);
                acc[j*2]   += vx[u] * f.x;
                acc[j*2+1] += vx[u] * f.y;
            }
        }
    }

    #pragma unroll
    for (int j = 0; j < 8; j++) acc[j] += __shfl_down_sync(~0u, acc[j], 16);

    float az[8];
    #pragma unroll
    for (int j = 0; j < 8; j++) az[j] = fmaxf(acc[j], 0.0f);

    float p = 0.0f;
    #pragma unroll
    for (int j = 0; j < 8; j++) p += az[j] * gw[128 + lo*8 + j];
    p += __shfl_xor_sync(~0u, p, 8);
    p += __shfl_xor_sync(~0u, p, 4);
    p += __shfl_xor_sync(~0u, p, 2);
    p += __shfl_xor_sync(~0u, p, 1);

    const float zv = d_hdot[row] + p;
    const float coeff = 1.0f / (1.0f + __expf(-zv));
    const float om = 1.0f - coeff;

    if (hw == 0) {
        float4 h4a = *(const float4*)&d_h[(size_t)row*Dn + lo*8];
        float4 h4b = *(const float4*)&d_h[(size_t)row*Dn + lo*8 + 4];
        float o[8];
        o[0] = coeff*h4a.x + om*az[0];
        o[1] = coeff*h4a.y + om*az[1];
        o[2] = coeff*h4a.z + om*az[2];
        o[3] = coeff*h4a.w + om*az[3];
        o[4] = coeff*h4b.x + om*az[4];
        o[5] = coeff*h4b.y + om*az[5];
        o[6] = coeff*h4b.z + om*az[6];
        o[7] = coeff*h4b.w + om*az[7];
        if (which == 2) {
            *(float4*)&outbuf[(size_t)row*Dn + lo*8]     = make_float4(o[0],o[1],o[2],o[3]);
            *(float4*)&outbuf[(size_t)row*Dn + lo*8 + 4] = make_float4(o[4],o[5],o[6],o[7]);
        } else {
            __half2 q0 = __floats2half2_rn(o[0], o[1]);
            __half2 q1 = __floats2half2_rn(o[2], o[3]);
            __half2 q2 = __floats2half2_rn(o[4], o[5]);
            __half2 q3 = __floats2half2_rn(o[6], o[7]);
            uint4 st;
            st.x = *reinterpret_cast<unsigned*>(&q0);
            st.y = *reinterpret_cast<unsigned*>(&q1);
            st.z = *reinterpret_cast<unsigned*>(&q2);
            st.w = *reinterpret_cast<unsigned*>(&q3);
            *(uint4*)&routh[(size_t)row*Dn + lo*8] = st;
        }
    }
}

// ---------------- launch ----------------
extern "C" void kernel_launch(void* const* d_in, const int* in_sizes, int n_in,
                              void* d_out, int out_size) {
    const float* x   = (const float*)d_in[0];
    const float* adj = (const float*)d_in[1];
    const float* Ww  = (const float*)d_in[2];
    const float* Wb  = (const float*)d_in[3];
    const float* A   = (const float*)d_in[4];
    const float* gw  = (const float*)d_in[5];
    const float* gb  = (const float*)d_in[6];
    float* out = (float*)d_out;

    cudaFuncSetAttribute(k_h, cudaFuncAttributeMaxDynamicSharedMemorySize, KH_SMEM);
    cudaFuncSetAttribute(k_g, cudaFuncAttributeMaxDynamicSharedMemorySize, KH_SMEM);

    k_init<<<64, 256>>>();
    k_h<<<KH_GRID, 128, KH_SMEM>>>(x, Ww, Wb);
    k_g<<<KH_GRID, 128, KH_SMEM>>>(A, gw, gb);
    k_buildE<<<dim3(Nn, Bn), 128>>>(adj);
    k_colfinal<<<64, 256>>>();
    k_attnorm<<<2048, 256>>>();
    k_hop<<<2048, 256>>>(0, gw, out);
    k_hop<<<2048, 256>>>(1, gw, out);
    k_hop<<<2048, 256>>>(2, gw, out);
}

// round 15
// speedup vs baseline: 1.0275x; 1.0275x over previous
#include <cuda_runtime.h>
#include <cuda_fp16.h>
#include <math.h>

#define Bn   16
#define Nn   1024
#define Dn   128
#define CAP  256     // max edges per row (mean ~52)

// ---------------- scratch (static device globals; no allocation) ----------------
__device__ __align__(16) float  d_h   [Bn*Nn*Dn];
__device__ __align__(16) __half d_hh  [Bn*Nn*Dn];    // half copy of h for gathers
__device__ __align__(16) float  d_g   [Bn*Nn*Dn];    // g' = h (A + A^T)
__device__ float  d_hdot[Bn*Nn];
__device__ int    d_colidx[Bn*Nn*CAP];
__device__ float  d_eval  [Bn*Nn*CAP];
__device__ int    d_rowcnt[Bn*Nn];
__device__ float  d_colZ  [Bn*Nn];
__device__ float  d_colinv[Bn*Nn];
__device__ __align__(16) __half d_r1h[Bn*Nn*Dn];
__device__ __align__(16) __half d_r2h[Bn*Nn*Dn];

// ---------------- packed fp32x2 FMA helpers (sm_100+) ----------------
__device__ __forceinline__ unsigned long long ffma2(unsigned long long a,
                                                    unsigned long long b,
                                                    unsigned long long c) {
    unsigned long long d;
    asm("fma.rn.f32x2 %0, %1, %2, %3;" : "=l"(d) : "l"(a), "l"(b), "l"(c));
    return d;
}
__device__ __forceinline__ unsigned long long pack2(float x) {
    unsigned long long d;
    asm("mov.b64 %0, {%1, %1};" : "=l"(d) : "f"(x));
    return d;
}
__device__ __forceinline__ unsigned long long packxy(float x, float y) {
    unsigned long long d;
    asm("mov.b64 %0, {%1, %2};" : "=l"(d) : "f"(x), "f"(y));
    return d;
}
__device__ __forceinline__ void unpack2(float& x, float& y, unsigned long long d) {
    asm("mov.b64 {%0, %1}, %2;" : "=f"(x), "=f"(y) : "l"(d));
}
union F4U { float4 f; unsigned long long u[2]; };

// ---------------- init: colZ starts at N ----------------
__global__ void k_init() {
    int t = blockIdx.x * blockDim.x + threadIdx.x;
    if (t < Bn*Nn) d_colZ[t] = (float)Nn;
}

// ================= dense GEMMs: 8 rows x 8 outs per thread, f32x2 math =================
#define KH_ROWS   64
#define KH_GRID   (Bn*Nn/KH_ROWS)      // 256
#define XT_STRIDE 68
#define KH_SMEM   ((128*132 + 128*XT_STRIDE + 128)*4)

// ---------------- k_h: h = x W^T + b (fp32 + half copy) ----------------
__global__ void __launch_bounds__(128) k_h(const float* __restrict__ x,
                                           const float* __restrict__ Ww,
                                           const float* __restrict__ Wb) {
    extern __shared__ float sm[];
    float* Wt = sm;                   // [128][132]  Wt[d][o] = W[o][d]
    float* xT = sm + 128*132;         // [128][68]

    const int t = threadIdx.x;
    const int ci = t & 15, ri = t >> 4;
    const int r0 = blockIdx.x * KH_ROWS;

    for (int i = t; i < 128*32; i += 128) {
        int o4 = i >> 7, d = i & 127;
        float4 v;
        v.x = Ww[(o4*4+0)*128 + d];
        v.y = Ww[(o4*4+1)*128 + d];
        v.z = Ww[(o4*4+2)*128 + d];
        v.w = Ww[(o4*4+3)*128 + d];
        *(float4*)&Wt[d*132 + o4*4] = v;
    }
    for (int i = t; i < 128*16; i += 128) {
        int row4 = i >> 7, k = i & 127;
        float4 v;
        v.x = x[(size_t)(r0+row4*4+0)*Dn + k];
        v.y = x[(size_t)(r0+row4*4+1)*Dn + k];
        v.z = x[(size_t)(r0+row4*4+2)*Dn + k];
        v.w = x[(size_t)(r0+row4*4+3)*Dn + k];
        *(float4*)&xT[k*XT_STRIDE + row4*4] = v;
    }
    __syncthreads();

    const float4 bA = *(const float4*)&Wb[ci*4];
    const float4 bB = *(const float4*)&Wb[64 + ci*4];
    unsigned long long acc[8][4];
    #pragma unroll
    for (int r = 0; r < 8; r++) {
        acc[r][0] = packxy(bA.x, bA.y);
        acc[r][1] = packxy(bA.z, bA.w);
        acc[r][2] = packxy(bB.x, bB.y);
        acc[r][3] = packxy(bB.z, bB.w);
    }

    #pragma unroll 4
    for (int k = 0; k < 128; k++) {
        F4U w0, w1;
        w0.f = *(float4*)&Wt[k*132 + ci*4];
        w1.f = *(float4*)&Wt[k*132 + 64 + ci*4];
        float4 xa = *(float4*)&xT[k*XT_STRIDE + ri*4];
        float4 xb = *(float4*)&xT[k*XT_STRIDE + 32 + ri*4];
        unsigned long long xp[8];
        xp[0] = pack2(xa.x); xp[1] = pack2(xa.y); xp[2] = pack2(xa.z); xp[3] = pack2(xa.w);
        xp[4] = pack2(xb.x); xp[5] = pack2(xb.y); xp[6] = pack2(xb.z); xp[7] = pack2(xb.w);
        #pragma unroll
        for (int r = 0; r < 8; r++) {
            acc[r][0] = ffma2(xp[r], w0.u[0], acc[r][0]);
            acc[r][1] = ffma2(xp[r], w0.u[1], acc[r][1]);
            acc[r][2] = ffma2(xp[r], w1.u[0], acc[r][2]);
            acc[r][3] = ffma2(xp[r], w1.u[1], acc[r][3]);
        }
    }

    #pragma unroll
    for (int r = 0; r < 8; r++) {
        const int row = r0 + ((r < 4) ? (ri*4 + r) : (32 + ri*4 + (r-4)));
        float o0,o1,o2,o3,p0,p1,p2,p3;
        unpack2(o0,o1,acc[r][0]); unpack2(o2,o3,acc[r][1]);
        unpack2(p0,p1,acc[r][2]); unpack2(p2,p3,acc[r][3]);
        *(float4*)&d_h[(size_t)row*Dn + ci*4]      = make_float4(o0,o1,o2,o3);
        *(float4*)&d_h[(size_t)row*Dn + 64 + ci*4] = make_float4(p0,p1,p2,p3);
        __half2 q0 = __floats2half2_rn(o0,o1), q1 = __floats2half2_rn(o2,o3);
        __half2 q2 = __floats2half2_rn(p0,p1), q3 = __floats2half2_rn(p2,p3);
        uint2 s0, s1;
        s0.x = *reinterpret_cast<unsigned*>(&q0); s0.y = *reinterpret_cast<unsigned*>(&q1);
        s1.x = *reinterpret_cast<unsigned*>(&q2); s1.y = *reinterpret_cast<unsigned*>(&q3);
        *(uint2*)&d_hh[(size_t)row*Dn + ci*4]      = s0;
        *(uint2*)&d_hh[(size_t)row*Dn + 64 + ci*4] = s1;
    }
}

// ---------------- k_g: g' = h (A + A^T) ; hdot = h.gw[0:128] + gb ----------------
__global__ void __launch_bounds__(128) k_g(const float* __restrict__ Am,
                                           const float* __restrict__ gw,
                                           const float* __restrict__ gb) {
    extern __shared__ float sm[];
    float* Ss = sm;                   // [128][132]
    float* hT = sm + 128*132;         // [128][68]
    float* gws = sm + 128*132 + 128*XT_STRIDE;

    const int t = threadIdx.x;
    const int ci = t & 15, ri = t >> 4;
    const int r0 = blockIdx.x * KH_ROWS;

    if (t < 128) gws[t] = gw[t];
    for (int i = t; i < 128*32; i += 128) {
        int o4 = i >> 7, d = i & 127;
        float4 a = *(const float4*)&Am[d*128 + o4*4];
        float4 v;
        v.x = a.x + Am[(o4*4+0)*128 + d];
        v.y = a.y + Am[(o4*4+1)*128 + d];
        v.z = a.z + Am[(o4*4+2)*128 + d];
        v.w = a.w + Am[(o4*4+3)*128 + d];
        *(float4*)&Ss[d*132 + o4*4] = v;
    }
    for (int i = t; i < 128*16; i += 128) {
        int row4 = i >> 7, k = i & 127;
        float4 v;
        v.x = d_h[(size_t)(r0+row4*4+0)*Dn + k];
        v.y = d_h[(size_t)(r0+row4*4+1)*Dn + k];
        v.z = d_h[(size_t)(r0+row4*4+2)*Dn + k];
        v.w = d_h[(size_t)(r0+row4*4+3)*Dn + k];
        *(float4*)&hT[k*XT_STRIDE + row4*4] = v;
    }
    __syncthreads();

    unsigned long long acc[8][4];
    #pragma unroll
    for (int r = 0; r < 8; r++)
        acc[r][0] = acc[r][1] = acc[r][2] = acc[r][3] = 0ull;

    #pragma unroll 4
    for (int k = 0; k < 128; k++) {
        F4U w0, w1;
        w0.f = *(float4*)&Ss[k*132 + ci*4];
        w1.f = *(float4*)&Ss[k*132 + 64 + ci*4];
        float4 xa = *(float4*)&hT[k*XT_STRIDE + ri*4];
        float4 xb = *(float4*)&hT[k*XT_STRIDE + 32 + ri*4];
        unsigned long long xp[8];
        xp[0] = pack2(xa.x); xp[1] = pack2(xa.y); xp[2] = pack2(xa.z); xp[3] = pack2(xa.w);
        xp[4] = pack2(xb.x); xp[5] = pack2(xb.y); xp[6] = pack2(xb.z); xp[7] = pack2(xb.w);
        #pragma unroll
        for (int r = 0; r < 8; r++) {
            acc[r][0] = ffma2(xp[r], w0.u[0], acc[r][0]);
            acc[r][1] = ffma2(xp[r], w0.u[1], acc[r][1]);
            acc[r][2] = ffma2(xp[r], w1.u[0], acc[r][2]);
            acc[r][3] = ffma2(xp[r], w1.u[1], acc[r][3]);
        }
    }

    #pragma unroll
    for (int r = 0; r < 8; r++) {
        const int row = r0 + ((r < 4) ? (ri*4 + r) : (32 + ri*4 + (r-4)));
        float o0,o1,o2,o3,p0,p1,p2,p3;
        unpack2(o0,o1,acc[r][0]); unpack2(o2,o3,acc[r][1]);
        unpack2(p0,p1,acc[r][2]); unpack2(p2,p3,acc[r][3]);
        *(float4*)&d_g[(size_t)row*Dn + ci*4]      = make_float4(o0,o1,o2,o3);
        *(float4*)&d_g[(size_t)row*Dn + 64 + ci*4] = make_float4(p0,p1,p2,p3);
    }

    if (t < KH_ROWS) {
        float p = 0.0f;
        #pragma unroll 8
        for (int k = 0; k < 128; k++)
            p += hT[k*XT_STRIDE + t] * gws[k];
        d_hdot[r0 + t] = p + gb[0];
    }
}

// ---------------- fused: atomic-free CSR + HFMA2 edge score (R13 2-edge form) ----------------
__global__ void __launch_bounds__(128) k_buildE(const float* __restrict__ adj) {
    const int i = blockIdx.x, b = blockIdx.y;
    const int row = b*Nn + i;
    __shared__ int   cols[CAP];
    __shared__ float P[128];
    __shared__ int   wtot[4];
    const int t = threadIdx.x, lane = t & 31, warp = t >> 5;
    P[t] = d_g[(size_t)row*Dn + t];

    // ---- register-bitmask CSR build: thread t covers cols {t*4..t*4+3, (t+128)*4..+3} ----
    const float4* a4 = (const float4*)(adj + (size_t)row * Nn);
    const float4 v0 = a4[t];
    const float4 v1 = a4[t + 128];
    unsigned my = 0;
    my |= (v0.x > 0.0f) ? 1u   : 0u;
    my |= (v0.y > 0.0f) ? 2u   : 0u;
    my |= (v0.z > 0.0f) ? 4u   : 0u;
    my |= (v0.w > 0.0f) ? 8u   : 0u;
    my |= (v1.x > 0.0f) ? 16u  : 0u;
    my |= (v1.y > 0.0f) ? 32u  : 0u;
    my |= (v1.z > 0.0f) ? 64u  : 0u;
    my |= (v1.w > 0.0f) ? 128u : 0u;
    const int mycnt = __popc(my);

    // warp inclusive prefix of counts
    int pre = mycnt;
    #pragma unroll
    for (int off = 1; off < 32; off <<= 1) {
        int nn = __shfl_up_sync(~0u, pre, off);
        if (lane >= off) pre += nn;
    }
    if (lane == 31) wtot[warp] = pre;
    __syncthreads();

    int base = pre - mycnt;
    int n = 0;
    #pragma unroll
    for (int w = 0; w < 4; w++) {
        int c = wtot[w];
        if (w < warp) base += c;
        n += c;
    }
    if (n > CAP) n = CAP;

    // write hits (predicated, register slot counter)
    {
        int slot = base;
        #pragma unroll
        for (int j = 0; j < 8; j++) {
            if (my & (1u << j)) {
                int col = (j < 4) ? (t*4 + j) : ((t + 128)*4 + (j - 4));
                if (slot < CAP) cols[slot] = col;
                slot++;
            }
        }
    }
    __syncthreads();

    const int n8 = (n + 7) & ~7;
    if (t == 0) d_rowcnt[row] = n8;
    for (int s = t; s < n; s += 128) d_colidx[(size_t)row*CAP + s] = cols[s];
    for (int s = n + t; s < n8; s += 128) {
        d_colidx[(size_t)row*CAP + s] = 0;
        d_eval  [(size_t)row*CAP + s] = 0.0f;
    }

    // ---- scoring: half2 row slice, HFMA2 accumulation (2-edge) ----
    const int lo8 = lane & 7, grp = lane >> 3;
    __half2 rg2[8];
    #pragma unroll
    for (int k = 0; k < 2; k++)
        #pragma unroll
        for (int j = 0; j < 4; j++)
            rg2[k*4+j] = __floats2half2_rn(P[k*64 + lo8*8 + j*2],
                                           P[k*64 + lo8*8 + j*2 + 1]);

    const __half* hb = d_hh + (size_t)b*Nn*Dn;
    const __half2 z2 = __floats2half2_rn(0.0f, 0.0f);
    for (int s0 = warp*4; s0 < n; s0 += 32) {
        const int sA = s0 + grp, sB = sA + 16;
        const int cA = cols[(sA < n) ? sA : 0];
        const int cB = cols[(sB < n) ? sB : 0];
        uint4 a0 = *(const uint4*)&hb[(size_t)cA*Dn +      lo8*8];
        uint4 a1 = *(const uint4*)&hb[(size_t)cA*Dn + 64 + lo8*8];
        uint4 b0 = *(const uint4*)&hb[(size_t)cB*Dn +      lo8*8];
        uint4 b1 = *(const uint4*)&hb[(size_t)cB*Dn + 64 + lo8*8];
        const __half2* ha0 = (const __half2*)&a0;
        const __half2* ha1 = (const __half2*)&a1;
        const __half2* hb0 = (const __half2*)&b0;
        const __half2* hb1 = (const __half2*)&b1;
        __half2 accA = z2, accB = z2;
        #pragma unroll
        for (int j = 0; j < 4; j++) {
            accA = __hfma2(rg2[j],   ha0[j], accA);
            accA = __hfma2(rg2[4+j], ha1[j], accA);
            accB = __hfma2(rg2[j],   hb0[j], accB);
            accB = __hfma2(rg2[4+j], hb1[j], accB);
        }
        float2 fA = __half22float2(accA);
        float2 fB = __half22float2(accB);
        float pA = fA.x + fA.y, pB = fB.x + fB.y;
        pA += __shfl_xor_sync(~0u, pA, 1); pB += __shfl_xor_sync(~0u, pB, 1);
        pA += __shfl_xor_sync(~0u, pA, 2); pB += __shfl_xor_sync(~0u, pB, 2);
        pA += __shfl_xor_sync(~0u, pA, 4); pB += __shfl_xor_sync(~0u, pB, 4);
        if (lo8 == 0) {
            if (sA < n) {
                float ev = __expf(pA);
                d_eval[(size_t)row*CAP + sA] = ev;
                atomicAdd(&d_colZ[b*Nn + cA], ev - 1.0f);
            }
            if (sB < n) {
                float ev = __expf(pB);
                d_eval[(size_t)row*CAP + sB] = ev;
                atomicAdd(&d_colZ[b*Nn + cB], ev - 1.0f);
            }
        }
    }
}

// ---------------- finalize: colinv = 1 / Z ----------------
__global__ void k_colfinal() {
    int t = blockIdx.x * blockDim.x + threadIdx.x;
    if (t < Bn*Nn)
        d_colinv[t] = 1.0f / d_colZ[t];
}

// ---------------- normalize all edge attention values in place ----------------
__global__ void k_attnorm() {
    const int lane = threadIdx.x & 31, warp = threadIdx.x >> 5;
    const int row  = blockIdx.x * 8 + warp;
    const int b    = row >> 10;
    const int n8   = d_rowcnt[row];
    const int*  ci = d_colidx + (size_t)row * CAP;
    float*      ev = d_eval   + (size_t)row * CAP;
    const float* cinv = d_colinv + b*Nn;
    for (int s = lane; s < n8; s += 32)
        ev[s] *= cinv[ci[s]];
}

// ---------------- hop: warp/row, smem-staged indices, 8 gathers in flight ----------------
__global__ void __launch_bounds__(256) k_hop(int which, const float* __restrict__ gw,
                                             float* __restrict__ outbuf) {
    const __half* rin = (which == 0) ? d_hh : (which == 1 ? d_r1h : d_r2h);
    __half* routh = (which == 0) ? d_r1h : d_r2h;

    __shared__ int   s_ci[8][CAP];
    __shared__ float s_ev[8][CAP];

    const int lane = threadIdx.x & 31, warp = threadIdx.x >> 5;
    const int row  = blockIdx.x * 8 + warp;
    const int b    = row >> 10;
    const int hw   = lane >> 4;
    const int lo   = lane & 15;

    const __half* rb = rin + (size_t)b * Nn * Dn;
    const int    n8  = d_rowcnt[row];
    {
        const int*   ci = d_colidx + (size_t)row * CAP;
        const float* ev = d_eval   + (size_t)row * CAP;
        for (int s = lane; s < n8; s += 32) {
            s_ci[warp][s] = ci[s];
            s_ev[warp][s] = ev[s];
        }
        __syncwarp();
    }

    float acc[8];
    #pragma unroll
    for (int j = 0; j < 8; j++) acc[j] = 0.0f;

    int s = 0;
    // main loop: 16 edges per step, 8 gathers in flight per thread
    for (; s + 16 <= n8; s += 16) {
        int cx[8]; float vx[8];
        #pragma unroll
        for (int u = 0; u < 8; u++) {
            const int sxx = s + u*2 + hw;
            cx[u] = s_ci[warp][sxx];
            vx[u] = s_ev[warp][sxx];
        }
        uint4 raw[8];
        #pragma unroll
        for (int u = 0; u < 8; u++)
            raw[u] = *(const uint4*)&rb[(size_t)cx[u]*Dn + lo*8];
        #pragma unroll
        for (int u = 0; u < 8; u++) {
            const __half2* h2 = (const __half2*)&raw[u];
            #pragma unroll
            for (int j = 0; j < 4; j++) {
                float2 f = __half22float2(h2[j]);
                acc[j*2]   += vx[u] * f.x;
                acc[j*2+1] += vx[u] * f.y;
            }
        }
    }
    // tail: 8 edges
    for (; s < n8; s += 8) {
        int cx[4]; float vx[4];
        #pragma unroll
        for (int u = 0; u < 4; u++) {
            const int sxx = s + u*2 + hw;
            cx[u] = s_ci[warp][sxx];
            vx[u] = s_ev[warp][sxx];
        }
        uint4 raw[4];
        #pragma unroll
        for (int u = 0; u < 4; u++)
            raw[u] = *(const uint4*)&rb[(size_t)cx[u]*Dn + lo*8];
        #pragma unroll
        for (int u = 0; u < 4; u++) {
            const __half2* h2 = (const __half2*)&raw[u];
            #pragma unroll
            for (int j = 0; j < 4; j++) {
                float2 f = __half22float2(h2[j]);
                acc[j*2]   += vx[u] * f.x;
                acc[j*2+1] += vx[u] * f.y;
            }
        }
    }

    #pragma unroll
    for (int j = 0; j < 8; j++) acc[j] += __shfl_down_sync(~0u, acc[j], 16);

    float az[8];
    #pragma unroll
    for (int j = 0; j < 8; j++) az[j] = fmaxf(acc[j], 0.0f);

    float p = 0.0f;
    #pragma unroll
    for (int j = 0; j < 8; j++) p += az[j] * gw[128 + lo*8 + j];
    p += __shfl_xor_sync(~0u, p, 8);
    p += __shfl_xor_sync(~0u, p, 4);
    p += __shfl_xor_sync(~0u, p, 2);
    p += __shfl_xor_sync(~0u, p, 1);

    const float zv = d_hdot[row] + p;
    const float coeff = 1.0f / (1.0f + __expf(-zv));
    const float om = 1.0f - coeff;

    if (hw == 0) {
        float4 h4a = *(const float4*)&d_h[(size_t)row*Dn + lo*8];
        float4 h4b = *(const float4*)&d_h[(size_t)row*Dn + lo*8 + 4];
        float o[8];
        o[0] = coeff*h4a.x + om*az[0];
        o[1] = coeff*h4a.y + om*az[1];
        o[2] = coeff*h4a.z + om*az[2];
        o[3] = coeff*h4a.w + om*az[3];
        o[4] = coeff*h4b.x + om*az[4];
        o[5] = coeff*h4b.y + om*az[5];
        o[6] = coeff*h4b.z + om*az[6];
        o[7] = coeff*h4b.w + om*az[7];
        if (which == 2) {
            *(float4*)&outbuf[(size_t)row*Dn + lo*8]     = make_float4(o[0],o[1],o[2],o[3]);
            *(float4*)&outbuf[(size_t)row*Dn + lo*8 + 4] = make_float4(o[4],o[5],o[6],o[7]);
        } else {
            __half2 q0 = __floats2half2_rn(o[0], o[1]);
            __half2 q1 = __floats2half2_rn(o[2], o[3]);
            __half2 q2 = __floats2half2_rn(o[4], o[5]);
            __half2 q3 = __floats2half2_rn(o[6], o[7]);
            uint4 st;
            st.x = *reinterpret_cast<unsigned*>(&q0);
            st.y = *reinterpret_cast<unsigned*>(&q1);
            st.z = *reinterpret_cast<unsigned*>(&q2);
            st.w = *reinterpret_cast<unsigned*>(&q3);
            *(uint4*)&routh[(size_t)row*Dn + lo*8] = st;
        }
    }
}

// ---------------- launch ----------------
extern "C" void kernel_launch(void* const* d_in, const int* in_sizes, int n_in,
                              void* d_out, int out_size) {
    const float* x   = (const float*)d_in[0];
    const float* adj = (const float*)d_in[1];
    const float* Ww  = (const float*)d_in[2];
    const float* Wb  = (const float*)d_in[3];
    const float* A   = (const float*)d_in[4];
    const float* gw  = (const float*)d_in[5];
    const float* gb  = (const float*)d_in[6];
    float* out = (float*)d_out;

    cudaFuncSetAttribute(k_h, cudaFuncAttributeMaxDynamicSharedMemorySize, KH_SMEM);
    cudaFuncSetAttribute(k_g, cudaFuncAttributeMaxDynamicSharedMemorySize, KH_SMEM);

    k_init<<<64, 256>>>();
    k_h<<<KH_GRID, 128, KH_SMEM>>>(x, Ww, Wb);
    k_g<<<KH_GRID, 128, KH_SMEM>>>(A, gw, gb);
    k_buildE<<<dim3(Nn, Bn), 128>>>(adj);
    k_colfinal<<<64, 256>>>();
    k_attnorm<<<2048, 256>>>();
    k_hop<<<2048, 256>>>(0, gw, out);
    k_hop<<<2048, 256>>>(1, gw, out);
    k_hop<<<2048, 256>>>(2, gw, out);
}

// round 16
// speedup vs baseline: 1.0630x; 1.0345x over previous
#include <cuda_runtime.h>
#include <cuda_fp16.h>
#include <math.h>

#define Bn   16
#define Nn   1024
#define Dn   128
#define CAP  256     // max edges per row (mean ~52)

// ---------------- scratch (static device globals; no allocation) ----------------
__device__ __align__(16) float  d_h   [Bn*Nn*Dn];
__device__ __align__(16) __half d_hh  [Bn*Nn*Dn];    // half copy of h for gathers
__device__ __align__(16) float  d_g   [Bn*Nn*Dn];    // g' = h (A + A^T)
__device__ float  d_hdot[Bn*Nn];
__device__ int    d_colidx[Bn*Nn*CAP];
__device__ float  d_eval  [Bn*Nn*CAP];
__device__ int    d_rowcnt[Bn*Nn];
__device__ float  d_colZ  [Bn*Nn];
__device__ float  d_colinv[Bn*Nn];
__device__ __align__(16) __half d_r1h[Bn*Nn*Dn];
__device__ __align__(16) __half d_r2h[Bn*Nn*Dn];

// ---------------- packed fp32x2 FMA helpers (sm_100+) ----------------
__device__ __forceinline__ unsigned long long ffma2(unsigned long long a,
                                                    unsigned long long b,
                                                    unsigned long long c) {
    unsigned long long d;
    asm("fma.rn.f32x2 %0, %1, %2, %3;" : "=l"(d) : "l"(a), "l"(b), "l"(c));
    return d;
}
__device__ __forceinline__ unsigned long long pack2(float x) {
    unsigned long long d;
    asm("mov.b64 %0, {%1, %1};" : "=l"(d) : "f"(x));
    return d;
}
__device__ __forceinline__ unsigned long long packxy(float x, float y) {
    unsigned long long d;
    asm("mov.b64 %0, {%1, %2};" : "=l"(d) : "f"(x), "f"(y));
    return d;
}
__device__ __forceinline__ void unpack2(float& x, float& y, unsigned long long d) {
    asm("mov.b64 {%0, %1}, %2;" : "=f"(x), "=f"(y) : "l"(d));
}
union F4U { float4 f; unsigned long long u[2]; };

// ================= dense GEMMs: 8 rows x 8 outs per thread, f32x2 math =================
#define KH_ROWS   64
#define KH_GRID   (Bn*Nn/KH_ROWS)      // 256
#define XT_STRIDE 68
#define KH_SMEM   ((128*132 + 128*XT_STRIDE + 128)*4)

// ---------------- k_h: h = x W^T + b (fp32 + half copy); also inits colZ ----------------
__global__ void __launch_bounds__(128) k_h(const float* __restrict__ x,
                                           const float* __restrict__ Ww,
                                           const float* __restrict__ Wb) {
    extern __shared__ float sm[];
    float* Wt = sm;                   // [128][132]  Wt[d][o] = W[o][d]
    float* xT = sm + 128*132;         // [128][68]

    const int t = threadIdx.x;
    const int ci = t & 15, ri = t >> 4;
    const int r0 = blockIdx.x * KH_ROWS;

    // init colZ for the 64 rows this block owns (runs before buildE on the stream)
    if (t < KH_ROWS) d_colZ[r0 + t] = (float)Nn;

    for (int i = t; i < 128*32; i += 128) {
        int o4 = i >> 7, d = i & 127;
        float4 v;
        v.x = Ww[(o4*4+0)*128 + d];
        v.y = Ww[(o4*4+1)*128 + d];
        v.z = Ww[(o4*4+2)*128 + d];
        v.w = Ww[(o4*4+3)*128 + d];
        *(float4*)&Wt[d*132 + o4*4] = v;
    }
    for (int i = t; i < 128*16; i += 128) {
        int row4 = i >> 7, k = i & 127;
        float4 v;
        v.x = x[(size_t)(r0+row4*4+0)*Dn + k];
        v.y = x[(size_t)(r0+row4*4+1)*Dn + k];
        v.z = x[(size_t)(r0+row4*4+2)*Dn + k];
        v.w = x[(size_t)(r0+row4*4+3)*Dn + k];
        *(float4*)&xT[k*XT_STRIDE + row4*4] = v;
    }
    __syncthreads();

    const float4 bA = *(const float4*)&Wb[ci*4];
    const float4 bB = *(const float4*)&Wb[64 + ci*4];
    unsigned long long acc[8][4];
    #pragma unroll
    for (int r = 0; r < 8; r++) {
        acc[r][0] = packxy(bA.x, bA.y);
        acc[r][1] = packxy(bA.z, bA.w);
        acc[r][2] = packxy(bB.x, bB.y);
        acc[r][3] = packxy(bB.z, bB.w);
    }

    #pragma unroll 4
    for (int k = 0; k < 128; k++) {
        F4U w0, w1;
        w0.f = *(float4*)&Wt[k*132 + ci*4];
        w1.f = *(float4*)&Wt[k*132 + 64 + ci*4];
        float4 xa = *(float4*)&xT[k*XT_STRIDE + ri*4];
        float4 xb = *(float4*)&xT[k*XT_STRIDE + 32 + ri*4];
        unsigned long long xp[8];
        xp[0] = pack2(xa.x); xp[1] = pack2(xa.y); xp[2] = pack2(xa.z); xp[3] = pack2(xa.w);
        xp[4] = pack2(xb.x); xp[5] = pack2(xb.y); xp[6] = pack2(xb.z); xp[7] = pack2(xb.w);
        #pragma unroll
        for (int r = 0; r < 8; r++) {
            acc[r][0] = ffma2(xp[r], w0.u[0], acc[r][0]);
            acc[r][1] = ffma2(xp[r], w0.u[1], acc[r][1]);
            acc[r][2] = ffma2(xp[r], w1.u[0], acc[r][2]);
            acc[r][3] = ffma2(xp[r], w1.u[1], acc[r][3]);
        }
    }

    #pragma unroll
    for (int r = 0; r < 8; r++) {
        const int row = r0 + ((r < 4) ? (ri*4 + r) : (32 + ri*4 + (r-4)));
        float o0,o1,o2,o3,p0,p1,p2,p3;
        unpack2(o0,o1,acc[r][0]); unpack2(o2,o3,acc[r][1]);
        unpack2(p0,p1,acc[r][2]); unpack2(p2,p3,acc[r][3]);
        *(float4*)&d_h[(size_t)row*Dn + ci*4]      = make_float4(o0,o1,o2,o3);
        *(float4*)&d_h[(size_t)row*Dn + 64 + ci*4] = make_float4(p0,p1,p2,p3);
        __half2 q0 = __floats2half2_rn(o0,o1), q1 = __floats2half2_rn(o2,o3);
        __half2 q2 = __floats2half2_rn(p0,p1), q3 = __floats2half2_rn(p2,p3);
        uint2 s0, s1;
        s0.x = *reinterpret_cast<unsigned*>(&q0); s0.y = *reinterpret_cast<unsigned*>(&q1);
        s1.x = *reinterpret_cast<unsigned*>(&q2); s1.y = *reinterpret_cast<unsigned*>(&q3);
        *(uint2*)&d_hh[(size_t)row*Dn + ci*4]      = s0;
        *(uint2*)&d_hh[(size_t)row*Dn + 64 + ci*4] = s1;
    }
}

// ---------------- k_g: g' = h (A + A^T) ; hdot = h.gw[0:128] + gb ----------------
__global__ void __launch_bounds__(128) k_g(const float* __restrict__ Am,
                                           const float* __restrict__ gw,
                                           const float* __restrict__ gb) {
    extern __shared__ float sm[];
    float* Ss = sm;                   // [128][132]
    float* hT = sm + 128*132;         // [128][68]
    float* gws = sm + 128*132 + 128*XT_STRIDE;

    const int t = threadIdx.x;
    const int ci = t & 15, ri = t >> 4;
    const int r0 = blockIdx.x * KH_ROWS;

    if (t < 128) gws[t] = gw[t];
    for (int i = t; i < 128*32; i += 128) {
        int o4 = i >> 7, d = i & 127;
        float4 a = *(const float4*)&Am[d*128 + o4*4];
        float4 v;
        v.x = a.x + Am[(o4*4+0)*128 + d];
        v.y = a.y + Am[(o4*4+1)*128 + d];
        v.z = a.z + Am[(o4*4+2)*128 + d];
        v.w = a.w + Am[(o4*4+3)*128 + d];
        *(float4*)&Ss[d*132 + o4*4] = v;
    }
    for (int i = t; i < 128*16; i += 128) {
        int row4 = i >> 7, k = i & 127;
        float4 v;
        v.x = d_h[(size_t)(r0+row4*4+0)*Dn + k];
        v.y = d_h[(size_t)(r0+row4*4+1)*Dn + k];
        v.z = d_h[(size_t)(r0+row4*4+2)*Dn + k];
        v.w = d_h[(size_t)(r0+row4*4+3)*Dn + k];
        *(float4*)&hT[k*XT_STRIDE + row4*4] = v;
    }
    __syncthreads();

    unsigned long long acc[8][4];
    #pragma unroll
    for (int r = 0; r < 8; r++)
        acc[r][0] = acc[r][1] = acc[r][2] = acc[r][3] = 0ull;

    #pragma unroll 4
    for (int k = 0; k < 128; k++) {
        F4U w0, w1;
        w0.f = *(float4*)&Ss[k*132 + ci*4];
        w1.f = *(float4*)&Ss[k*132 + 64 + ci*4];
        float4 xa = *(float4*)&hT[k*XT_STRIDE + ri*4];
        float4 xb = *(float4*)&hT[k*XT_STRIDE + 32 + ri*4];
        unsigned long long xp[8];
        xp[0] = pack2(xa.x); xp[1] = pack2(xa.y); xp[2] = pack2(xa.z); xp[3] = pack2(xa.w);
        xp[4] = pack2(xb.x); xp[5] = pack2(xb.y); xp[6] = pack2(xb.z); xp[7] = pack2(xb.w);
        #pragma unroll
        for (int r = 0; r < 8; r++) {
            acc[r][0] = ffma2(xp[r], w0.u[0], acc[r][0]);
            acc[r][1] = ffma2(xp[r], w0.u[1], acc[r][1]);
            acc[r][2] = ffma2(xp[r], w1.u[0], acc[r][2]);
            acc[r][3] = ffma2(xp[r], w1.u[1], acc[r][3]);
        }
    }

    #pragma unroll
    for (int r = 0; r < 8; r++) {
        const int row = r0 + ((r < 4) ? (ri*4 + r) : (32 + ri*4 + (r-4)));
        float o0,o1,o2,o3,p0,p1,p2,p3;
        unpack2(o0,o1,acc[r][0]); unpack2(o2,o3,acc[r][1]);
        unpack2(p0,p1,acc[r][2]); unpack2(p2,p3,acc[r][3]);
        *(float4*)&d_g[(size_t)row*Dn + ci*4]      = make_float4(o0,o1,o2,o3);
        *(float4*)&d_g[(size_t)row*Dn + 64 + ci*4] = make_float4(p0,p1,p2,p3);
    }

    if (t < KH_ROWS) {
        float p = 0.0f;
        #pragma unroll 8
        for (int k = 0; k < 128; k++)
            p += hT[k*XT_STRIDE + t] * gws[k];
        d_hdot[r0 + t] = p + gb[0];
    }
}

// ---------------- fused: atomic-free CSR + HFMA2 edge score ----------------
__global__ void __launch_bounds__(128) k_buildE(const float* __restrict__ adj) {
    const int i = blockIdx.x, b = blockIdx.y;
    const int row = b*Nn + i;
    __shared__ int   cols[CAP];
    __shared__ float P[128];
    __shared__ int   wtot[4];
    const int t = threadIdx.x, lane = t & 31, warp = t >> 5;
    P[t] = d_g[(size_t)row*Dn + t];

    // ---- register-bitmask CSR build: thread t covers cols {t*4..t*4+3, (t+128)*4..+3} ----
    const float4* a4 = (const float4*)(adj + (size_t)row * Nn);
    const float4 v0 = a4[t];
    const float4 v1 = a4[t + 128];
    unsigned my = 0;
    my |= (v0.x > 0.0f) ? 1u   : 0u;
    my |= (v0.y > 0.0f) ? 2u   : 0u;
    my |= (v0.z > 0.0f) ? 4u   : 0u;
    my |= (v0.w > 0.0f) ? 8u   : 0u;
    my |= (v1.x > 0.0f) ? 16u  : 0u;
    my |= (v1.y > 0.0f) ? 32u  : 0u;
    my |= (v1.z > 0.0f) ? 64u  : 0u;
    my |= (v1.w > 0.0f) ? 128u : 0u;
    const int mycnt = __popc(my);

    int pre = mycnt;
    #pragma unroll
    for (int off = 1; off < 32; off <<= 1) {
        int nn = __shfl_up_sync(~0u, pre, off);
        if (lane >= off) pre += nn;
    }
    if (lane == 31) wtot[warp] = pre;
    __syncthreads();

    int base = pre - mycnt;
    int n = 0;
    #pragma unroll
    for (int w = 0; w < 4; w++) {
        int c = wtot[w];
        if (w < warp) base += c;
        n += c;
    }
    if (n > CAP) n = CAP;

    {
        int slot = base;
        #pragma unroll
        for (int j = 0; j < 8; j++) {
            if (my & (1u << j)) {
                int col = (j < 4) ? (t*4 + j) : ((t + 128)*4 + (j - 4));
                if (slot < CAP) cols[slot] = col;
                slot++;
            }
        }
    }
    __syncthreads();

    const int n8 = (n + 7) & ~7;
    if (t == 0) d_rowcnt[row] = n8;
    for (int s = t; s < n; s += 128) d_colidx[(size_t)row*CAP + s] = cols[s];
    for (int s = n + t; s < n8; s += 128) {
        d_colidx[(size_t)row*CAP + s] = 0;
        d_eval  [(size_t)row*CAP + s] = 0.0f;
    }

    // ---- scoring: half2 row slice, HFMA2 accumulation (2-edge) ----
    const int lo8 = lane & 7, grp = lane >> 3;
    __half2 rg2[8];
    #pragma unroll
    for (int k = 0; k < 2; k++)
        #pragma unroll
        for (int j = 0; j < 4; j++)
            rg2[k*4+j] = __floats2half2_rn(P[k*64 + lo8*8 + j*2],
                                           P[k*64 + lo8*8 + j*2 + 1]);

    const __half* hb = d_hh + (size_t)b*Nn*Dn;
    const __half2 z2 = __floats2half2_rn(0.0f, 0.0f);
    for (int s0 = warp*4; s0 < n; s0 += 32) {
        const int sA = s0 + grp, sB = sA + 16;
        const int cA = cols[(sA < n) ? sA : 0];
        const int cB = cols[(sB < n) ? sB : 0];
        uint4 a0 = *(const uint4*)&hb[(size_t)cA*Dn +      lo8*8];
        uint4 a1 = *(const uint4*)&hb[(size_t)cA*Dn + 64 + lo8*8];
        uint4 b0 = *(const uint4*)&hb[(size_t)cB*Dn +      lo8*8];
        uint4 b1 = *(const uint4*)&hb[(size_t)cB*Dn + 64 + lo8*8];
        const __half2* ha0 = (const __half2*)&a0;
        const __half2* ha1 = (const __half2*)&a1;
        const __half2* hb0 = (const __half2*)&b0;
        const __half2* hb1 = (const __half2*)&b1;
        __half2 accA = z2, accB = z2;
        #pragma unroll
        for (int j = 0; j < 4; j++) {
            accA = __hfma2(rg2[j],   ha0[j], accA);
            accA = __hfma2(rg2[4+j], ha1[j], accA);
            accB = __hfma2(rg2[j],   hb0[j], accB);
            accB = __hfma2(rg2[4+j], hb1[j], accB);
        }
        float2 fA = __half22float2(accA);
        float2 fB = __half22float2(accB);
        float pA = fA.x + fA.y, pB = fB.x + fB.y;
        pA += __shfl_xor_sync(~0u, pA, 1); pB += __shfl_xor_sync(~0u, pB, 1);
        pA += __shfl_xor_sync(~0u, pA, 2); pB += __shfl_xor_sync(~0u, pB, 2);
        pA += __shfl_xor_sync(~0u, pA, 4); pB += __shfl_xor_sync(~0u, pB, 4);
        if (lo8 == 0) {
            if (sA < n) {
                float ev = __expf(pA);
                d_eval[(size_t)row*CAP + sA] = ev;
                atomicAdd(&d_colZ[b*Nn + cA], ev - 1.0f);
            }
            if (sB < n) {
                float ev = __expf(pB);
                d_eval[(size_t)row*CAP + sB] = ev;
                atomicAdd(&d_colZ[b*Nn + cB], ev - 1.0f);
            }
        }
    }
}

// ---------------- finalize: colinv = 1 / Z ----------------
__global__ void k_colfinal() {
    int t = blockIdx.x * blockDim.x + threadIdx.x;
    if (t < Bn*Nn)
        d_colinv[t] = 1.0f / d_colZ[t];
}

// ---------------- hop: warp/row, smem-staged indices, 8 gathers in flight;
//                  hop0 normalizes att during staging ----------------
__global__ void __launch_bounds__(256) k_hop(int which, const float* __restrict__ gw,
                                             float* __restrict__ outbuf) {
    const __half* rin = (which == 0) ? d_hh : (which == 1 ? d_r1h : d_r2h);
    __half* routh = (which == 0) ? d_r1h : d_r2h;

    __shared__ int   s_ci[8][CAP];
    __shared__ float s_ev[8][CAP];

    const int lane = threadIdx.x & 31, warp = threadIdx.x >> 5;
    const int row  = blockIdx.x * 8 + warp;
    const int b    = row >> 10;
    const int hw   = lane >> 4;
    const int lo   = lane & 15;

    const __half* rb = rin + (size_t)b * Nn * Dn;
    const int    n8  = d_rowcnt[row];
    {
        const int*   ci = d_colidx + (size_t)row * CAP;
        float*       ev = d_eval   + (size_t)row * CAP;
        if (which == 0) {
            const float* cinv = d_colinv + b*Nn;
            for (int s = lane; s < n8; s += 32) {
                const int c = ci[s];
                const float v = ev[s] * cinv[c];
                s_ci[warp][s] = c;
                s_ev[warp][s] = v;
                ev[s] = v;                 // persist normalized att for hops 1,2
            }
        } else {
            for (int s = lane; s < n8; s += 32) {
                s_ci[warp][s] = ci[s];
                s_ev[warp][s] = ev[s];
            }
        }
        __syncwarp();
    }

    float acc[8];
    #pragma unroll
    for (int j = 0; j < 8; j++) acc[j] = 0.0f;

    int s = 0;
    // main loop: 16 edges per step, 8 gathers in flight per thread
    for (; s + 16 <= n8; s += 16) {
        int cx[8]; float vx[8];
        #pragma unroll
        for (int u = 0; u < 8; u++) {
            const int sxx = s + u*2 + hw;
            cx[u] = s_ci[warp][sxx];
            vx[u] = s_ev[warp][sxx];
        }
        uint4 raw[8];
        #pragma unroll
        for (int u = 0; u < 8; u++)
            raw[u] = *(const uint4*)&rb[(size_t)cx[u]*Dn + lo*8];
        #pragma unroll
        for (int u = 0; u < 8; u++) {
            const __half2* h2 = (const __half2*)&raw[u];
            #pragma unroll
            for (int j = 0; j < 4; j++) {
                float2 f = __half22float2(h2[j]);
                acc[j*2]   += vx[u] * f.x;
                acc[j*2+1] += vx[u] * f.y;
            }
        }
    }
    // tail: 8 edges
    for (; s < n8; s += 8) {
        int cx[4]; float vx[4];
        #pragma unroll
        for (int u = 0; u < 4; u++) {
            const int sxx = s + u*2 + hw;
            cx[u] = s_ci[warp][sxx];
            vx[u] = s_ev[warp][sxx];
        }
        uint4 raw[4];
        #pragma unroll
        for (int u = 0; u < 4; u++)
            raw[u] = *(const uint4*)&rb[(size_t)cx[u]*Dn + lo*8];
        #pragma unroll
        for (int u = 0; u < 4; u++) {
            const __half2* h2 = (const __half2*)&raw[u];
            #pragma unroll
            for (int j = 0; j < 4; j++) {
                float2 f = __half22float2(h2[j]);
                acc[j*2]   += vx[u] * f.x;
                acc[j*2+1] += vx[u] * f.y;
            }
        }
    }

    #pragma unroll
    for (int j = 0; j < 8; j++) acc[j] += __shfl_down_sync(~0u, acc[j], 16);

    float az[8];
    #pragma unroll
    for (int j = 0; j < 8; j++) az[j] = fmaxf(acc[j], 0.0f);

    float p = 0.0f;
    #pragma unroll
    for (int j = 0; j < 8; j++) p += az[j] * gw[128 + lo*8 + j];
    p += __shfl_xor_sync(~0u, p, 8);
    p += __shfl_xor_sync(~0u, p, 4);
    p += __shfl_xor_sync(~0u, p, 2);
    p += __shfl_xor_sync(~0u, p, 1);

    const float zv = d_hdot[row] + p;
    const float coeff = 1.0f / (1.0f + __expf(-zv));
    const float om = 1.0f - coeff;

    if (hw == 0) {
        float4 h4a = *(const float4*)&d_h[(size_t)row*Dn + lo*8];
        float4 h4b = *(const float4*)&d_h[(size_t)row*Dn + lo*8 + 4];
        float o[8];
        o[0] = coeff*h4a.x + om*az[0];
        o[1] = coeff*h4a.y + om*az[1];
        o[2] = coeff*h4a.z + om*az[2];
        o[3] = coeff*h4a.w + om*az[3];
        o[4] = coeff*h4b.x + om*az[4];
        o[5] = coeff*h4b.y + om*az[5];
        o[6] = coeff*h4b.z + om*az[6];
        o[7] = coeff*h4b.w + om*az[7];
        if (which == 2) {
            *(float4*)&outbuf[(size_t)row*Dn + lo*8]     = make_float4(o[0],o[1],o[2],o[3]);
            *(float4*)&outbuf[(size_t)row*Dn + lo*8 + 4] = make_float4(o[4],o[5],o[6],o[7]);
        } else {
            __half2 q0 = __floats2half2_rn(o[0], o[1]);
            __half2 q1 = __floats2half2_rn(o[2], o[3]);
            __half2 q2 = __floats2half2_rn(o[4], o[5]);
            __half2 q3 = __floats2half2_rn(o[6], o[7]);
            uint4 st;
            st.x = *reinterpret_cast<unsigned*>(&q0);
            st.y = *reinterpret_cast<unsigned*>(&q1);
            st.z = *reinterpret_cast<unsigned*>(&q2);
            st.w = *reinterpret_cast<unsigned*>(&q3);
            *(uint4*)&routh[(size_t)row*Dn + lo*8] = st;
        }
    }
}

// ---------------- launch ----------------
extern "C" void kernel_launch(void* const* d_in, const int* in_sizes, int n_in,
                              void* d_out, int out_size) {
    const float* x   = (const float*)d_in[0];
    const float* adj = (const float*)d_in[1];
    const float* Ww  = (const float*)d_in[2];
    const float* Wb  = (const float*)d_in[3];
    const float* A   = (const float*)d_in[4];
    const float* gw  = (const float*)d_in[5];
    const float* gb  = (const float*)d_in[6];
    float* out = (float*)d_out;

    cudaFuncSetAttribute(k_h, cudaFuncAttributeMaxDynamicSharedMemorySize, KH_SMEM);
    cudaFuncSetAttribute(k_g, cudaFuncAttributeMaxDynamicSharedMemorySize, KH_SMEM);

    k_h<<<KH_GRID, 128, KH_SMEM>>>(x, Ww, Wb);
    k_g<<<KH_GRID, 128, KH_SMEM>>>(A, gw, gb);
    k_buildE<<<dim3(Nn, Bn), 128>>>(adj);
    k_colfinal<<<64, 256>>>();
    k_hop<<<2048, 256>>>(0, gw, out);
    k_hop<<<2048, 256>>>(1, gw, out);
    k_hop<<<2048, 256>>>(2, gw, out);
}

// round 17
// speedup vs baseline: 1.0778x; 1.0139x over previous
#include <cuda_runtime.h>
#include <cuda_fp16.h>
#include <math.h>

#define Bn   16
#define Nn   1024
#define Dn   128
#define CAP  256     // max edges per row (mean ~52)

// ---------------- scratch (static device globals; no allocation) ----------------
__device__ __align__(16) float  d_h   [Bn*Nn*Dn];
__device__ __align__(16) __half d_hh  [Bn*Nn*Dn];    // half copy of h for gathers
__device__ __align__(16) float  d_g   [Bn*Nn*Dn];    // g' = h (A + A^T)
__device__ float  d_hdot[Bn*Nn];
__device__ int    d_colidx[Bn*Nn*CAP];
__device__ float  d_eval  [Bn*Nn*CAP];
__device__ int    d_rowcnt[Bn*Nn];
__device__ float  d_colZ  [Bn*Nn];
__device__ __align__(16) __half d_r1h[Bn*Nn*Dn];
__device__ __align__(16) __half d_r2h[Bn*Nn*Dn];

// ---------------- packed fp32x2 FMA helpers (sm_100+) ----------------
__device__ __forceinline__ unsigned long long ffma2(unsigned long long a,
                                                    unsigned long long b,
                                                    unsigned long long c) {
    unsigned long long d;
    asm("fma.rn.f32x2 %0, %1, %2, %3;" : "=l"(d) : "l"(a), "l"(b), "l"(c));
    return d;
}
__device__ __forceinline__ unsigned long long pack2(float x) {
    unsigned long long d;
    asm("mov.b64 %0, {%1, %1};" : "=l"(d) : "f"(x));
    return d;
}
__device__ __forceinline__ unsigned long long packxy(float x, float y) {
    unsigned long long d;
    asm("mov.b64 %0, {%1, %2};" : "=l"(d) : "f"(x), "f"(y));
    return d;
}
__device__ __forceinline__ void unpack2(float& x, float& y, unsigned long long d) {
    asm("mov.b64 {%0, %1}, %2;" : "=f"(x), "=f"(y) : "l"(d));
}
union F4U { float4 f; unsigned long long u[2]; };

// ================= dense GEMMs: 8 rows x 8 outs per thread, f32x2 math =================
#define KH_ROWS   64
#define KH_GRID   (Bn*Nn/KH_ROWS)      // 256
#define XT_STRIDE 68
#define KH_SMEM   ((128*132 + 128*XT_STRIDE + 128)*4)

// ---------------- k_h: h = x W^T + b (fp32 + half copy); also inits colZ ----------------
__global__ void __launch_bounds__(128) k_h(const float* __restrict__ x,
                                           const float* __restrict__ Ww,
                                           const float* __restrict__ Wb) {
    extern __shared__ float sm[];
    float* Wt = sm;                   // [128][132]  Wt[d][o] = W[o][d]
    float* xT = sm + 128*132;         // [128][68]

    const int t = threadIdx.x;
    const int ci = t & 15, ri = t >> 4;
    const int r0 = blockIdx.x * KH_ROWS;

    // init colZ for the 64 rows this block owns (runs before buildE on the stream)
    if (t < KH_ROWS) d_colZ[r0 + t] = (float)Nn;

    for (int i = t; i < 128*32; i += 128) {
        int o4 = i >> 7, d = i & 127;
        float4 v;
        v.x = Ww[(o4*4+0)*128 + d];
        v.y = Ww[(o4*4+1)*128 + d];
        v.z = Ww[(o4*4+2)*128 + d];
        v.w = Ww[(o4*4+3)*128 + d];
        *(float4*)&Wt[d*132 + o4*4] = v;
    }
    for (int i = t; i < 128*16; i += 128) {
        int row4 = i >> 7, k = i & 127;
        float4 v;
        v.x = x[(size_t)(r0+row4*4+0)*Dn + k];
        v.y = x[(size_t)(r0+row4*4+1)*Dn + k];
        v.z = x[(size_t)(r0+row4*4+2)*Dn + k];
        v.w = x[(size_t)(r0+row4*4+3)*Dn + k];
        *(float4*)&xT[k*XT_STRIDE + row4*4] = v;
    }
    __syncthreads();

    const float4 bA = *(const float4*)&Wb[ci*4];
    const float4 bB = *(const float4*)&Wb[64 + ci*4];
    unsigned long long acc[8][4];
    #pragma unroll
    for (int r = 0; r < 8; r++) {
        acc[r][0] = packxy(bA.x, bA.y);
        acc[r][1] = packxy(bA.z, bA.w);
        acc[r][2] = packxy(bB.x, bB.y);
        acc[r][3] = packxy(bB.z, bB.w);
    }

    #pragma unroll 4
    for (int k = 0; k < 128; k++) {
        F4U w0, w1;
        w0.f = *(float4*)&Wt[k*132 + ci*4];
        w1.f = *(float4*)&Wt[k*132 + 64 + ci*4];
        float4 xa = *(float4*)&xT[k*XT_STRIDE + ri*4];
        float4 xb = *(float4*)&xT[k*XT_STRIDE + 32 + ri*4];
        unsigned long long xp[8];
        xp[0] = pack2(xa.x); xp[1] = pack2(xa.y); xp[2] = pack2(xa.z); xp[3] = pack2(xa.w);
        xp[4] = pack2(xb.x); xp[5] = pack2(xb.y); xp[6] = pack2(xb.z); xp[7] = pack2(xb.w);
        #pragma unroll
        for (int r = 0; r < 8; r++) {
            acc[r][0] = ffma2(xp[r], w0.u[0], acc[r][0]);
            acc[r][1] = ffma2(xp[r], w0.u[1], acc[r][1]);
            acc[r][2] = ffma2(xp[r], w1.u[0], acc[r][2]);
            acc[r][3] = ffma2(xp[r], w1.u[1], acc[r][3]);
        }
    }

    #pragma unroll
    for (int r = 0; r < 8; r++) {
        const int row = r0 + ((r < 4) ? (ri*4 + r) : (32 + ri*4 + (r-4)));
        float o0,o1,o2,o3,p0,p1,p2,p3;
        unpack2(o0,o1,acc[r][0]); unpack2(o2,o3,acc[r][1]);
        unpack2(p0,p1,acc[r][2]); unpack2(p2,p3,acc[r][3]);
        *(float4*)&d_h[(size_t)row*Dn + ci*4]      = make_float4(o0,o1,o2,o3);
        *(float4*)&d_h[(size_t)row*Dn + 64 + ci*4] = make_float4(p0,p1,p2,p3);
        __half2 q0 = __floats2half2_rn(o0,o1), q1 = __floats2half2_rn(o2,o3);
        __half2 q2 = __floats2half2_rn(p0,p1), q3 = __floats2half2_rn(p2,p3);
        uint2 s0, s1;
        s0.x = *reinterpret_cast<unsigned*>(&q0); s0.y = *reinterpret_cast<unsigned*>(&q1);
        s1.x = *reinterpret_cast<unsigned*>(&q2); s1.y = *reinterpret_cast<unsigned*>(&q3);
        *(uint2*)&d_hh[(size_t)row*Dn + ci*4]      = s0;
        *(uint2*)&d_hh[(size_t)row*Dn + 64 + ci*4] = s1;
    }
}

// ---------------- k_g: g' = h (A + A^T) ; hdot = h.gw[0:128] + gb ----------------
__global__ void __launch_bounds__(128) k_g(const float* __restrict__ Am,
                                           const float* __restrict__ gw,
                                           const float* __restrict__ gb) {
    extern __shared__ float sm[];
    float* Ss = sm;                   // [128][132]
    float* hT = sm + 128*132;         // [128][68]
    float* gws = sm + 128*132 + 128*XT_STRIDE;

    const int t = threadIdx.x;
    const int ci = t & 15, ri = t >> 4;
    const int r0 = blockIdx.x * KH_ROWS;

    if (t < 128) gws[t] = gw[t];
    for (int i = t; i < 128*32; i += 128) {
        int o4 = i >> 7, d = i & 127;
        float4 a = *(const float4*)&Am[d*128 + o4*4];
        float4 v;
        v.x = a.x + Am[(o4*4+0)*128 + d];
        v.y = a.y + Am[(o4*4+1)*128 + d];
        v.z = a.z + Am[(o4*4+2)*128 + d];
        v.w = a.w + Am[(o4*4+3)*128 + d];
        *(float4*)&Ss[d*132 + o4*4] = v;
    }
    for (int i = t; i < 128*16; i += 128) {
        int row4 = i >> 7, k = i & 127;
        float4 v;
        v.x = d_h[(size_t)(r0+row4*4+0)*Dn + k];
        v.y = d_h[(size_t)(r0+row4*4+1)*Dn + k];
        v.z = d_h[(size_t)(r0+row4*4+2)*Dn + k];
        v.w = d_h[(size_t)(r0+row4*4+3)*Dn + k];
        *(float4*)&hT[k*XT_STRIDE + row4*4] = v;
    }
    __syncthreads();

    unsigned long long acc[8][4];
    #pragma unroll
    for (int r = 0; r < 8; r++)
        acc[r][0] = acc[r][1] = acc[r][2] = acc[r][3] = 0ull;

    #pragma unroll 4
    for (int k = 0; k < 128; k++) {
        F4U w0, w1;
        w0.f = *(float4*)&Ss[k*132 + ci*4];
        w1.f = *(float4*)&Ss[k*132 + 64 + ci*4];
        float4 xa = *(float4*)&hT[k*XT_STRIDE + ri*4];
        float4 xb = *(float4*)&hT[k*XT_STRIDE + 32 + ri*4];
        unsigned long long xp[8];
        xp[0] = pack2(xa.x); xp[1] = pack2(xa.y); xp[2] = pack2(xa.z); xp[3] = pack2(xa.w);
        xp[4] = pack2(xb.x); xp[5] = pack2(xb.y); xp[6] = pack2(xb.z); xp[7] = pack2(xb.w);
        #pragma unroll
        for (int r = 0; r < 8; r++) {
            acc[r][0] = ffma2(xp[r], w0.u[0], acc[r][0]);
            acc[r][1] = ffma2(xp[r], w0.u[1], acc[r][1]);
            acc[r][2] = ffma2(xp[r], w1.u[0], acc[r][2]);
            acc[r][3] = ffma2(xp[r], w1.u[1], acc[r][3]);
        }
    }

    #pragma unroll
    for (int r = 0; r < 8; r++) {
        const int row = r0 + ((r < 4) ? (ri*4 + r) : (32 + ri*4 + (r-4)));
        float o0,o1,o2,o3,p0,p1,p2,p3;
        unpack2(o0,o1,acc[r][0]); unpack2(o2,o3,acc[r][1]);
        unpack2(p0,p1,acc[r][2]); unpack2(p2,p3,acc[r][3]);
        *(float4*)&d_g[(size_t)row*Dn + ci*4]      = make_float4(o0,o1,o2,o3);
        *(float4*)&d_g[(size_t)row*Dn + 64 + ci*4] = make_float4(p0,p1,p2,p3);
    }

    if (t < KH_ROWS) {
        float p = 0.0f;
        #pragma unroll 8
        for (int k = 0; k < 128; k++)
            p += hT[k*XT_STRIDE + t] * gws[k];
        d_hdot[r0 + t] = p + gb[0];
    }
}

// ---------------- fused: atomic-free CSR + HFMA2 edge score ----------------
__global__ void __launch_bounds__(128) k_buildE(const float* __restrict__ adj) {
    const int i = blockIdx.x, b = blockIdx.y;
    const int row = b*Nn + i;
    __shared__ int   cols[CAP];
    __shared__ float P[128];
    __shared__ int   wtot[4];
    const int t = threadIdx.x, lane = t & 31, warp = t >> 5;
    P[t] = d_g[(size_t)row*Dn + t];

    // ---- register-bitmask CSR build: thread t covers cols {t*4..t*4+3, (t+128)*4..+3} ----
    const float4* a4 = (const float4*)(adj + (size_t)row * Nn);
    const float4 v0 = a4[t];
    const float4 v1 = a4[t + 128];
    unsigned my = 0;
    my |= (v0.x > 0.0f) ? 1u   : 0u;
    my |= (v0.y > 0.0f) ? 2u   : 0u;
    my |= (v0.z > 0.0f) ? 4u   : 0u;
    my |= (v0.w > 0.0f) ? 8u   : 0u;
    my |= (v1.x > 0.0f) ? 16u  : 0u;
    my |= (v1.y > 0.0f) ? 32u  : 0u;
    my |= (v1.z > 0.0f) ? 64u  : 0u;
    my |= (v1.w > 0.0f) ? 128u : 0u;
    const int mycnt = __popc(my);

    int pre = mycnt;
    #pragma unroll
    for (int off = 1; off < 32; off <<= 1) {
        int nn = __shfl_up_sync(~0u, pre, off);
        if (lane >= off) pre += nn;
    }
    if (lane == 31) wtot[warp] = pre;
    __syncthreads();

    int base = pre - mycnt;
    int n = 0;
    #pragma unroll
    for (int w = 0; w < 4; w++) {
        int c = wtot[w];
        if (w < warp) base += c;
        n += c;
    }
    if (n > CAP) n = CAP;

    {
        int slot = base;
        #pragma unroll
        for (int j = 0; j < 8; j++) {
            if (my & (1u << j)) {
                int col = (j < 4) ? (t*4 + j) : ((t + 128)*4 + (j - 4));
                if (slot < CAP) cols[slot] = col;
                slot++;
            }
        }
    }
    __syncthreads();

    const int n8 = (n + 7) & ~7;
    if (t == 0) d_rowcnt[row] = n8;
    for (int s = t; s < n; s += 128) d_colidx[(size_t)row*CAP + s] = cols[s];
    for (int s = n + t; s < n8; s += 128) {
        d_colidx[(size_t)row*CAP + s] = 0;
        d_eval  [(size_t)row*CAP + s] = 0.0f;
    }

    // ---- scoring: half2 row slice, HFMA2 accumulation (2-edge) ----
    const int lo8 = lane & 7, grp = lane >> 3;
    __half2 rg2[8];
    #pragma unroll
    for (int k = 0; k < 2; k++)
        #pragma unroll
        for (int j = 0; j < 4; j++)
            rg2[k*4+j] = __floats2half2_rn(P[k*64 + lo8*8 + j*2],
                                           P[k*64 + lo8*8 + j*2 + 1]);

    const __half* hb = d_hh + (size_t)b*Nn*Dn;
    const __half2 z2 = __floats2half2_rn(0.0f, 0.0f);
    for (int s0 = warp*4; s0 < n; s0 += 32) {
        const int sA = s0 + grp, sB = sA + 16;
        const int cA = cols[(sA < n) ? sA : 0];
        const int cB = cols[(sB < n) ? sB : 0];
        uint4 a0 = *(const uint4*)&hb[(size_t)cA*Dn +      lo8*8];
        uint4 a1 = *(const uint4*)&hb[(size_t)cA*Dn + 64 + lo8*8];
        uint4 b0 = *(const uint4*)&hb[(size_t)cB*Dn +      lo8*8];
        uint4 b1 = *(const uint4*)&hb[(size_t)cB*Dn + 64 + lo8*8];
        const __half2* ha0 = (const __half2*)&a0;
        const __half2* ha1 = (const __half2*)&a1;
        const __half2* hb0 = (const __half2*)&b0;
        const __half2* hb1 = (const __half2*)&b1;
        __half2 accA = z2, accB = z2;
        #pragma unroll
        for (int j = 0; j < 4; j++) {
            accA = __hfma2(rg2[j],   ha0[j], accA);
            accA = __hfma2(rg2[4+j], ha1[j], accA);
            accB = __hfma2(rg2[j],   hb0[j], accB);
            accB = __hfma2(rg2[4+j], hb1[j], accB);
        }
        float2 fA = __half22float2(accA);
        float2 fB = __half22float2(accB);
        float pA = fA.x + fA.y, pB = fB.x + fB.y;
        pA += __shfl_xor_sync(~0u, pA, 1); pB += __shfl_xor_sync(~0u, pB, 1);
        pA += __shfl_xor_sync(~0u, pA, 2); pB += __shfl_xor_sync(~0u, pB, 2);
        pA += __shfl_xor_sync(~0u, pA, 4); pB += __shfl_xor_sync(~0u, pB, 4);
        if (lo8 == 0) {
            if (sA < n) {
                float ev = __expf(pA);
                d_eval[(size_t)row*CAP + sA] = ev;
                atomicAdd(&d_colZ[b*Nn + cA], ev - 1.0f);
            }
            if (sB < n) {
                float ev = __expf(pB);
                d_eval[(size_t)row*CAP + sB] = ev;
                atomicAdd(&d_colZ[b*Nn + cB], ev - 1.0f);
            }
        }
    }
}

// ---------------- hop: warp/row, smem-staged indices, 8 gathers in flight;
//                  hop0 normalizes att (1/colZ via IEEE rcp) during staging ----------------
__global__ void __launch_bounds__(256) k_hop(int which, const float* __restrict__ gw,
                                             float* __restrict__ outbuf) {
    const __half* rin = (which == 0) ? d_hh : (which == 1 ? d_r1h : d_r2h);
    __half* routh = (which == 0) ? d_r1h : d_r2h;

    __shared__ int   s_ci[8][CAP];
    __shared__ float s_ev[8][CAP];

    const int lane = threadIdx.x & 31, warp = threadIdx.x >> 5;
    const int row  = blockIdx.x * 8 + warp;
    const int b    = row >> 10;
    const int hw   = lane >> 4;
    const int lo   = lane & 15;

    const __half* rb = rin + (size_t)b * Nn * Dn;
    const int    n8  = d_rowcnt[row];
    {
        const int*   ci = d_colidx + (size_t)row * CAP;
        float*       ev = d_eval   + (size_t)row * CAP;
        if (which == 0) {
            const float* cz = d_colZ + b*Nn;
            for (int s = lane; s < n8; s += 32) {
                const int c = ci[s];
                const float v = ev[s] * __frcp_rn(cz[c]);
                s_ci[warp][s] = c;
                s_ev[warp][s] = v;
                ev[s] = v;                 // persist normalized att for hops 1,2
            }
        } else {
            for (int s = lane; s < n8; s += 32) {
                s_ci[warp][s] = ci[s];
                s_ev[warp][s] = ev[s];
            }
        }
        __syncwarp();
    }

    float acc[8];
    #pragma unroll
    for (int j = 0; j < 8; j++) acc[j] = 0.0f;

    int s = 0;
    // main loop: 16 edges per step, 8 gathers in flight per thread
    for (; s + 16 <= n8; s += 16) {
        int cx[8]; float vx[8];
        #pragma unroll
        for (int u = 0; u < 8; u++) {
            const int sxx = s + u*2 + hw;
            cx[u] = s_ci[warp][sxx];
            vx[u] = s_ev[warp][sxx];
        }
        uint4 raw[8];
        #pragma unroll
        for (int u = 0; u < 8; u++)
            raw[u] = *(const uint4*)&rb[(size_t)cx[u]*Dn + lo*8];
        #pragma unroll
        for (int u = 0; u < 8; u++) {
            const __half2* h2 = (const __half2*)&raw[u];
            #pragma unroll
            for (int j = 0; j < 4; j++) {
                float2 f = __half22float2(h2[j]);
                acc[j*2]   += vx[u] * f.x;
                acc[j*2+1] += vx[u] * f.y;
            }
        }
    }
    // tail: 8 edges
    for (; s < n8; s += 8) {
        int cx[4]; float vx[4];
        #pragma unroll
        for (int u = 0; u < 4; u++) {
            const int sxx = s + u*2 + hw;
            cx[u] = s_ci[warp][sxx];
            vx[u] = s_ev[warp][sxx];
        }
        uint4 raw[4];
        #pragma unroll
        for (int u = 0; u < 4; u++)
            raw[u] = *(const uint4*)&rb[(size_t)cx[u]*Dn + lo*8];
        #pragma unroll
        for (int u = 0; u < 4; u++) {
            const __half2* h2 = (const __half2*)&raw[u];
            #pragma unroll
            for (int j = 0; j < 4; j++) {
                float2 f = __half22float2(h2[j]);
                acc[j*2]   += vx[u] * f.x;
                acc[j*2+1] += vx[u] * f.y;
            }
        }
    }

    #pragma unroll
    for (int j = 0; j < 8; j++) acc[j] += __shfl_down_sync(~0u, acc[j], 16);

    float az[8];
    #pragma unroll
    for (int j = 0; j < 8; j++) az[j] = fmaxf(acc[j], 0.0f);

    float p = 0.0f;
    #pragma unroll
    for (int j = 0; j < 8; j++) p += az[j] * gw[128 + lo*8 + j];
    p += __shfl_xor_sync(~0u, p, 8);
    p += __shfl_xor_sync(~0u, p, 4);
    p += __shfl_xor_sync(~0u, p, 2);
    p += __shfl_xor_sync(~0u, p, 1);

    const float zv = d_hdot[row] + p;
    const float coeff = 1.0f / (1.0f + __expf(-zv));
    const float om = 1.0f - coeff;

    if (hw == 0) {
        float4 h4a = *(const float4*)&d_h[(size_t)row*Dn + lo*8];
        float4 h4b = *(const float4*)&d_h[(size_t)row*Dn + lo*8 + 4];
        float o[8];
        o[0] = coeff*h4a.x + om*az[0];
        o[1] = coeff*h4a.y + om*az[1];
        o[2] = coeff*h4a.z + om*az[2];
        o[3] = coeff*h4a.w + om*az[3];
        o[4] = coeff*h4b.x + om*az[4];
        o[5] = coeff*h4b.y + om*az[5];
        o[6] = coeff*h4b.z + om*az[6];
        o[7] = coeff*h4b.w + om*az[7];
        if (which == 2) {
            *(float4*)&outbuf[(size_t)row*Dn + lo*8]     = make_float4(o[0],o[1],o[2],o[3]);
            *(float4*)&outbuf[(size_t)row*Dn + lo*8 + 4] = make_float4(o[4],o[5],o[6],o[7]);
        } else {
            __half2 q0 = __floats2half2_rn(o[0], o[1]);
            __half2 q1 = __floats2half2_rn(o[2], o[3]);
            __half2 q2 = __floats2half2_rn(o[4], o[5]);
            __half2 q3 = __floats2half2_rn(o[6], o[7]);
            uint4 st;
            st.x = *reinterpret_cast<unsigned*>(&q0);
            st.y = *reinterpret_cast<unsigned*>(&q1);
            st.z = *reinterpret_cast<unsigned*>(&q2);
            st.w = *reinterpret_cast<unsigned*>(&q3);
            *(uint4*)&routh[(size_t)row*Dn + lo*8] = st;
        }
    }
}

// ---------------- launch ----------------
extern "C" void kernel_launch(void* const* d_in, const int* in_sizes, int n_in,
                              void* d_out, int out_size) {
    const float* x   = (const float*)d_in[0];
    const float* adj = (const float*)d_in[1];
    const float* Ww  = (const float*)d_in[2];
    const float* Wb  = (const float*)d_in[3];
    const float* A   = (const float*)d_in[4];
    const float* gw  = (const float*)d_in[5];
    const float* gb  = (const float*)d_in[6];
    float* out = (float*)d_out;

    cudaFuncSetAttribute(k_h, cudaFuncAttributeMaxDynamicSharedMemorySize, KH_SMEM);
    cudaFuncSetAttribute(k_g, cudaFuncAttributeMaxDynamicSharedMemorySize, KH_SMEM);

    k_h<<<KH_GRID, 128, KH_SMEM>>>(x, Ww, Wb);
    k_g<<<KH_GRID, 128, KH_SMEM>>>(A, gw, gb);
    k_buildE<<<dim3(Nn, Bn), 128>>>(adj);
    k_hop<<<2048, 256>>>(0, gw, out);
    k_hop<<<2048, 256>>>(1, gw, out);
    k_hop<<<2048, 256>>>(2, gw, out);
}